// round 12
// baseline (speedup 1.0000x reference)
#include <cuda_runtime.h>

// v' = A*v + B*i  (A = 0.625, B = 0.075), warp-cooperative affine scan.
// R12 = R9 with the warm-up bug fixed: tile_scan256 consumes 256 elements
// (64 float4s) starting at its pointer, so the second-half warm-up must
// start at p-64 (the full 256 elements preceding the half-row), NOT p-32
// (which overlapped 128 elements INTO the half-row and shifted the carry).
// A^256 underflows fp32 exactly -> 256-step warm-up from v=0 equals the
// full-history carry to fp32 precision. Tile carries are exact (b31).
// Scheduling: warp-per-half-row, 8192 warp-tasks = 0.86 wave at the
// 64-warp/SM cap -> single wave, high sustained occupancy, no barriers.

#define NN     4096
#define TT     8192
#define HALF   (TT / 2)            // 4096 steps per warp
#define TILES  (HALF / 256)        // 16 tiles of 256

#define A1f 0.625f
#define A2f 0.390625f
#define A3f 0.244140625f
#define A4f 0.152587890625f
#define A5f 0.095367431640625f
#define A6f 0.059604644775390625f
#define A7f 0.037252902984619140625f
#define A8f 0.02328306436538696289f
#define A16f 5.4210108624275222e-4f
#define A32f 2.9387358770557188e-7f
#define A64f 8.6361685550944446e-14f
#define A128f 7.4583407312002067e-27f
#define Bf  0.075f

// Scan 256 elements at p (2 float4/lane, p[0..63]); optionally store to q.
// Returns carry-out (= b31 exactly; A^256 underflows to 0, so carry-in
// only affects the stored prefix P, never the returned summary).
template <bool STORE>
__device__ __forceinline__ float tile_scan256(const float4* __restrict__ p,
                                              float4* __restrict__ q,
                                              float carry, float apl, int lane)
{
    float4 xa = __ldcs(p + 2 * lane);
    float4 xb = __ldcs(p + 2 * lane + 1);

    float c0 = Bf * xa.x;
    float c1 = fmaf(A1f, c0, Bf * xa.y);
    float c2 = fmaf(A1f, c1, Bf * xa.z);
    float c3 = fmaf(A1f, c2, Bf * xa.w);
    float c4 = fmaf(A1f, c3, Bf * xb.x);
    float c5 = fmaf(A1f, c4, Bf * xb.y);
    float c6 = fmaf(A1f, c5, Bf * xb.z);
    float c7 = fmaf(A1f, c6, Bf * xb.w);

    float b = c7, t;
    t = __shfl_up_sync(0xffffffffu, b, 1);  if (lane >= 1)  b = fmaf(A8f,   t, b);
    t = __shfl_up_sync(0xffffffffu, b, 2);  if (lane >= 2)  b = fmaf(A16f,  t, b);
    t = __shfl_up_sync(0xffffffffu, b, 4);  if (lane >= 4)  b = fmaf(A32f,  t, b);
    t = __shfl_up_sync(0xffffffffu, b, 8);  if (lane >= 8)  b = fmaf(A64f,  t, b);
    t = __shfl_up_sync(0xffffffffu, b, 16); if (lane >= 16) b = fmaf(A128f, t, b);

    if (STORE) {
        float bp = __shfl_up_sync(0xffffffffu, b, 1);
        if (lane == 0) bp = 0.0f;
        float P = fmaf(apl, carry, bp);

        float4 ya, yb;
        ya.x = fmaf(A1f, P, c0);
        ya.y = fmaf(A2f, P, c1);
        ya.z = fmaf(A3f, P, c2);
        ya.w = fmaf(A4f, P, c3);
        yb.x = fmaf(A5f, P, c4);
        yb.y = fmaf(A6f, P, c5);
        yb.z = fmaf(A7f, P, c6);
        yb.w = fmaf(A8f, P, c7);
        __stcs(q + 2 * lane, ya);
        __stcs(q + 2 * lane + 1, yb);
    }

    return __shfl_sync(0xffffffffu, b, 31);
}

__global__ __launch_bounds__(128, 16)
void nonspiking_halfrow_kernel(const float* __restrict__ in, float* __restrict__ out)
{
    int task = (blockIdx.x * blockDim.x + threadIdx.x) >> 5;  // 0..8191
    int lane = threadIdx.x & 31;
    int row  = task >> 1;
    int half = task & 1;

    size_t base = (size_t)row * TT + (size_t)half * HALF;
    const float4* p = reinterpret_cast<const float4*>(in  + base);
    float4*       q = reinterpret_cast<float4*>(out + base);

    // apl = A^(8*lane) by square-and-multiply
    float apl = 1.0f, aa = A8f;
    int e = lane;
    #pragma unroll
    for (int k = 0; k < 5; ++k) { if (e & 1) apl *= aa; aa *= aa; e >>= 1; }

    float carry = 0.0f;
    if (half) {
        // Warm-up: the FULL 256 elements immediately preceding this
        // half-row (p[-64..-1] float4s). carry = exact fp32 state at base.
        carry = tile_scan256<false>(p - 64, nullptr, 0.0f, apl, lane);
    }

    #pragma unroll 4
    for (int t = 0; t < TILES; ++t) {
        carry = tile_scan256<true>(p + t * 64, q + t * 64, carry, apl, lane);
    }
}

extern "C" void kernel_launch(void* const* d_in, const int* in_sizes, int n_in,
                              void* d_out, int out_size)
{
    const float* in = (const float*)d_in[0];
    float* out = (float*)d_out;
    (void)in_sizes; (void)n_in; (void)out_size;

    int block = 128;                    // 4 warps
    int grid = NN * 2 * 32 / block;     // 2048 CTAs -> single wave @16/SM cap
    nonspiking_halfrow_kernel<<<grid, block>>>(in, out);
}

// round 15
// speedup vs baseline: 1.0319x; 1.0319x over previous
#include <cuda_runtime.h>

// v' = A*v + B*i  (A = 0.625, B = 0.075), block-cooperative affine scan.
// R13 = R7 (best kernel: CTA per row, 4KB tiles, exact A^256-underflow
// carries, <=32 regs via __launch_bounds__(128,16), 84% occ) with ONE
// controlled change: default .wb stores instead of __stcs, letting L2
// batch dirty-line writebacks into DRAM-page-friendly bursts to improve
// the R/W-mixed DRAM efficiency that caps us at ~65% dram active.

#define NN     4096
#define TT     8192
#define TILES  (TT / 1024)         // 8 CTA-tiles of 1024 floats per row

#define A1f 0.625f
#define A2f 0.390625f
#define A3f 0.244140625f
#define A4f 0.152587890625f
#define A5f 0.095367431640625f
#define A6f 0.059604644775390625f
#define A7f 0.037252902984619140625f
#define A8f 0.02328306436538696289f
#define A16f 5.4210108624275222e-4f
#define A32f 2.9387358770557188e-7f
#define A64f 8.6361685550944446e-14f
#define A128f 7.4583407312002067e-27f
#define Bf  0.075f

__global__ __launch_bounds__(128, 16)
void nonspiking_blockscan_wb_kernel(const float* __restrict__ in,
                                    float* __restrict__ out)
{
    __shared__ float s_b31[2][4];     // [tile parity][warp] summaries

    int row  = blockIdx.x;
    int w    = threadIdx.x >> 5;
    int lane = threadIdx.x & 31;

    // warp w owns floats [t*1024 + w*256 + lane*8, +8)
    const float4* p = reinterpret_cast<const float4*>(in  + (size_t)row * TT) + w * 64;
    float4*       q = reinterpret_cast<float4*>(out + (size_t)row * TT) + w * 64;

    // apl = A^(8*lane) by square-and-multiply
    float apl = 1.0f, aa = A8f;
    int e = lane;
    #pragma unroll
    for (int k = 0; k < 5; ++k) { if (e & 1) apl *= aa; aa *= aa; e >>= 1; }

    float carry = 0.0f;
    #pragma unroll
    for (int t = 0; t < TILES; ++t) {
        // CTA-wide 4KB contiguous read (two LDG.128 per lane, streaming).
        float4 xa = __ldcs(p + t * 256 + 2 * lane);
        float4 xb = __ldcs(p + t * 256 + 2 * lane + 1);

        // Local cumulative terms for this lane's 8 steps.
        float c0 = Bf * xa.x;
        float c1 = fmaf(A1f, c0, Bf * xa.y);
        float c2 = fmaf(A1f, c1, Bf * xa.z);
        float c3 = fmaf(A1f, c2, Bf * xa.w);
        float c4 = fmaf(A1f, c3, Bf * xb.x);
        float c5 = fmaf(A1f, c4, Bf * xb.y);
        float c6 = fmaf(A1f, c5, Bf * xb.z);
        float c7 = fmaf(A1f, c6, Bf * xb.w);

        // Kogge-Stone over lane summaries (step-s multiplier = A^(8s)).
        float b = c7, s;
        s = __shfl_up_sync(0xffffffffu, b, 1);  if (lane >= 1)  b = fmaf(A8f,   s, b);
        s = __shfl_up_sync(0xffffffffu, b, 2);  if (lane >= 2)  b = fmaf(A16f,  s, b);
        s = __shfl_up_sync(0xffffffffu, b, 4);  if (lane >= 4)  b = fmaf(A32f,  s, b);
        s = __shfl_up_sync(0xffffffffu, b, 8);  if (lane >= 8)  b = fmaf(A64f,  s, b);
        s = __shfl_up_sync(0xffffffffu, b, 16); if (lane >= 16) b = fmaf(A128f, s, b);

        // Publish warp summary (lane 31 holds this warp's segment scan).
        if (lane == 31) s_b31[t & 1][w] = b;
        __syncthreads();

        // Warp carry-in: tile carry for warp 0, else b31 of warp w-1
        // (older terms carry A^256 = 0 exactly in fp32).
        float cw = (w == 0) ? carry : s_b31[t & 1][w - 1];

        float bp = __shfl_up_sync(0xffffffffu, b, 1);
        if (lane == 0) bp = 0.0f;
        float P = fmaf(apl, cw, bp);

        float4 ya, yb;
        ya.x = fmaf(A1f, P, c0);
        ya.y = fmaf(A2f, P, c1);
        ya.z = fmaf(A3f, P, c2);
        ya.w = fmaf(A4f, P, c3);
        yb.x = fmaf(A5f, P, c4);
        yb.y = fmaf(A6f, P, c5);
        yb.z = fmaf(A7f, P, c6);
        yb.w = fmaf(A8f, P, c7);
        q[t * 256 + 2 * lane]     = ya;   // default .wb: let L2 batch writebacks
        q[t * 256 + 2 * lane + 1] = yb;

        carry = s_b31[t & 1][3];          // tile carry = warp 3's b31
    }
}

extern "C" void kernel_launch(void* const* d_in, const int* in_sizes, int n_in,
                              void* d_out, int out_size)
{
    const float* in = (const float*)d_in[0];
    float* out = (float*)d_out;
    (void)in_sizes; (void)n_in; (void)out_size;

    nonspiking_blockscan_wb_kernel<<<NN, 128>>>(in, out);  // one CTA per row
}